// round 1
// baseline (speedup 1.0000x reference)
#include <cuda_runtime.h>
#include <math.h>

#define Bv 4
#define Lv 1024
#define Dv 1024
#define Hv 16
#define HDv 64
#define Fv 2816
#define Av 64
#define Pv 30
#define KTOT (Pv + Lv)          /* 1054 keys incl. prefix */
#define NKT 17                  /* ceil(1054/64) key tiles */
#define SROW 1088               /* NKT*64, padded score row */

// ---------------- scratch (static device globals; no allocations) ----------
__device__ float g_xn[Bv*Lv*Dv];
__device__ float g_q [Bv*Lv*Dv];
__device__ float g_k [Bv*Lv*Dv];
__device__ float g_v [Bv*Lv*Dv];
__device__ float g_att[Bv*Lv*Dv];
__device__ float g_x [Bv*Lv*Dv];
__device__ float g_y [Bv*Lv*Dv];
__device__ float g_h0[Bv*Lv*Fv];
__device__ float g_h1[Bv*Lv*Fv];
__device__ float g_az[Bv*Lv*Av];

__device__ __forceinline__ float gelu_f(float x) {
    float x3 = x * x * x;
    return 0.5f * x * (1.0f + tanhf(0.7978845608028654f * (x + 0.044715f * x3)));
}

// ---------------- RMSNorm ---------------------------------------------------
__global__ __launch_bounds__(256) void rmsnorm_kernel(
    const float* __restrict__ x, const float* __restrict__ w, float* __restrict__ o)
{
    int row = blockIdx.x;
    const float* xr = x + (size_t)row * Dv;
    float* orow = o + (size_t)row * Dv;
    int tid = threadIdx.x;
    int d0 = tid * 4;                      // 256 threads * 4 = 1024
    float4 v = *(const float4*)&xr[d0];
    float s = v.x*v.x + v.y*v.y + v.z*v.z + v.w*v.w;
    #pragma unroll
    for (int off = 16; off; off >>= 1) s += __shfl_xor_sync(0xffffffffu, s, off);
    __shared__ float red[8];
    __shared__ float inv_s;
    if ((tid & 31) == 0) red[tid >> 5] = s;
    __syncthreads();
    if (tid == 0) {
        float t = 0.f;
        #pragma unroll
        for (int i = 0; i < 8; i++) t += red[i];
        inv_s = rsqrtf(t * (1.0f / Dv) + 1e-6f);
    }
    __syncthreads();
    float inv = inv_s;
    float4 wv = *(const float4*)&w[d0];
    float4 r;
    r.x = v.x*inv*wv.x; r.y = v.y*inv*wv.y; r.z = v.z*inv*wv.z; r.w = v.w*inv*wv.w;
    *(float4*)&orow[d0] = r;
}

// ---------------- SGEMM 128x128x16, 256 thr, 8x8 microtile ------------------
// C[M,N] = epilogue( alpha * A[M,K] @ B[K,N] )
// epilogue: +res[idx] if res; then *gelu(gate[idx]) if gate.
// Requires: M%128==0, N%128==0, K%16==0.
__global__ __launch_bounds__(256) void sgemm_kernel(
    const float* __restrict__ A, const float* __restrict__ B, float* __restrict__ C,
    int M, int N, int K, float alpha,
    const float* __restrict__ res, const float* __restrict__ gate)
{
    __shared__ float As[16][132];   // transposed A tile, padded
    __shared__ float Bs[16][128];

    int tid = threadIdx.x;
    int m0 = blockIdx.y * 128;
    int n0 = blockIdx.x * 128;
    int tx = tid & 15;              // col group
    int ty = tid >> 4;              // row group

    int ar = tid >> 2;              // A row (0..63), two passes (+64)
    int ac = (tid & 3) * 4;         // A k-offset
    int br = tid >> 5;              // B row (0..7), two passes (+8)
    int bc = (tid & 31) * 4;        // B n-offset

    float acc[8][8];
    #pragma unroll
    for (int i = 0; i < 8; i++)
        #pragma unroll
        for (int j = 0; j < 8; j++) acc[i][j] = 0.f;

    for (int k0 = 0; k0 < K; k0 += 16) {
        #pragma unroll
        for (int p = 0; p < 2; p++) {
            int row = ar + p * 64;
            float4 va = *(const float4*)&A[(size_t)(m0 + row) * K + k0 + ac];
            As[ac + 0][row] = va.x;
            As[ac + 1][row] = va.y;
            As[ac + 2][row] = va.z;
            As[ac + 3][row] = va.w;
        }
        #pragma unroll
        for (int p = 0; p < 2; p++) {
            int row = br + p * 8;
            *(float4*)&Bs[row][bc] = *(const float4*)&B[(size_t)(k0 + row) * N + n0 + bc];
        }
        __syncthreads();
        #pragma unroll
        for (int kk = 0; kk < 16; kk++) {
            float a[8], b[8];
            float4 a0 = *(const float4*)&As[kk][ty * 8];
            float4 a1 = *(const float4*)&As[kk][ty * 8 + 4];
            a[0]=a0.x; a[1]=a0.y; a[2]=a0.z; a[3]=a0.w;
            a[4]=a1.x; a[5]=a1.y; a[6]=a1.z; a[7]=a1.w;
            float4 b0 = *(const float4*)&Bs[kk][tx * 4];
            float4 b1 = *(const float4*)&Bs[kk][tx * 4 + 64];
            b[0]=b0.x; b[1]=b0.y; b[2]=b0.z; b[3]=b0.w;
            b[4]=b1.x; b[5]=b1.y; b[6]=b1.z; b[7]=b1.w;
            #pragma unroll
            for (int i = 0; i < 8; i++)
                #pragma unroll
                for (int j = 0; j < 8; j++) acc[i][j] += a[i] * b[j];
        }
        __syncthreads();
    }

    #pragma unroll
    for (int i = 0; i < 8; i++) {
        int m = m0 + ty * 8 + i;
        #pragma unroll
        for (int jh = 0; jh < 2; jh++) {
            int n = n0 + tx * 4 + jh * 64;
            size_t idx = (size_t)m * N + n;
            float vv[4];
            #pragma unroll
            for (int u = 0; u < 4; u++) vv[u] = acc[i][jh * 4 + u] * alpha;
            if (res) {
                float4 rv = *(const float4*)&res[idx];
                vv[0] += rv.x; vv[1] += rv.y; vv[2] += rv.z; vv[3] += rv.w;
            }
            if (gate) {
                float4 gv = *(const float4*)&gate[idx];
                vv[0] *= gelu_f(gv.x); vv[1] *= gelu_f(gv.y);
                vv[2] *= gelu_f(gv.z); vv[3] *= gelu_f(gv.w);
            }
            float4 outv; outv.x = vv[0]; outv.y = vv[1]; outv.z = vv[2]; outv.w = vv[3];
            *(float4*)&C[idx] = outv;
        }
    }
}

// ---------------- Attention (two-pass, prefix KV, optional causal+bias) -----
// grid: (L/32, B*H), block 256. q already scaled by HD^-0.5.
// layouts: q/k/v/out [B, L, H, HD]; prefix [B, 2, P, H, HD].
#define ATTN_SMEM ((32*SROW + 32*64 + 64*68 + 32) * 4)

__global__ __launch_bounds__(256) void attn_kernel(
    const float* __restrict__ qb, const float* __restrict__ kb, const float* __restrict__ vb,
    const float* __restrict__ pkb, const float* __restrict__ pvb,
    const float* __restrict__ relpos, float* __restrict__ ob,
    int sel, int causal)
{
    extern __shared__ float sm[];
    float* S      = sm;                    // [32][SROW]
    float* Qs     = S + 32 * SROW;         // [32][64]
    float* Ks     = Qs + 32 * 64;          // [64][68] (reused for V)
    float* relrow = Ks + 64 * 68;          // [32]

    int tid = threadIdx.x;
    int bh = blockIdx.y;
    int b = bh >> 4, h = bh & 15;
    int q0 = blockIdx.x * 32;

    // load Q tile
    {
        int r  = tid >> 3;
        int c0 = (tid & 7) * 8;
        const float* src = qb + ((size_t)(b * Lv + q0 + r) * Hv + h) * HDv + c0;
        float4 v0 = *(const float4*)src;
        float4 v1 = *(const float4*)(src + 4);
        *(float4*)&Qs[r * 64 + c0]     = v0;
        *(float4*)&Qs[r * 64 + c0 + 4] = v1;
    }
    if (causal && tid < 32) relrow[tid] = relpos[h * 32 + tid];
    __syncthreads();

    int qrb = tid >> 6;       // 0..3 (constant per warp)
    int kk  = tid & 63;

    // ---- pass 1: scores ----
    for (int t = 0; t < NKT; t++) {
        {
            int r = tid >> 2;
            int g = t * 64 + r;
            bool valid = g < KTOT;
            const float* src;
            if (g < Pv) src = pkb + (((size_t)(b * 2 + sel) * Pv + g) * Hv + h) * HDv;
            else        src = kb  + ((size_t)(b * Lv + (g - Pv)) * Hv + h) * HDv;
            int c = (tid & 3) * 4;
            #pragma unroll
            for (int p = 0; p < 4; p++) {
                int cc = c + p * 16;
                float4 v = valid ? *(const float4*)(src + cc) : make_float4(0.f, 0.f, 0.f, 0.f);
                *(float4*)&Ks[r * 68 + cc] = v;
            }
        }
        __syncthreads();

        float sc[8];
        #pragma unroll
        for (int i = 0; i < 8; i++) sc[i] = 0.f;
        #pragma unroll
        for (int db = 0; db < 64; db += 16) {
            float kr[16];
            #pragma unroll
            for (int u = 0; u < 16; u += 4) {
                float4 v = *(const float4*)&Ks[kk * 68 + db + u];
                kr[u] = v.x; kr[u+1] = v.y; kr[u+2] = v.z; kr[u+3] = v.w;
            }
            #pragma unroll
            for (int i = 0; i < 8; i++) {
                const float* qp = &Qs[(qrb + i * 4) * 64 + db];
                #pragma unroll
                for (int u = 0; u < 16; u += 4) {
                    float4 v = *(const float4*)(qp + u);
                    sc[i] += v.x * kr[u] + v.y * kr[u+1] + v.z * kr[u+2] + v.w * kr[u+3];
                }
            }
        }
        int g = t * 64 + kk;
        #pragma unroll
        for (int i = 0; i < 8; i++) {
            int q = qrb + i * 4;
            float val = sc[i];
            if (g >= KTOT) {
                val = -1e10f;
            } else if (causal && g >= Pv) {
                int kp = g - Pv;
                int qp = q0 + q;
                if (kp > qp) val = -1e10f;
                else {
                    int rel = qp - kp;
                    int bkt;
                    if (rel < 16) bkt = rel;
                    else {
                        bkt = 16 + (int)(logf((float)rel * 0.0625f) *
                                         (16.0f / 2.0794415416798357f));
                        if (bkt > 31) bkt = 31;
                    }
                    val += relrow[bkt];
                }
            }
            S[q * SROW + g] = val;
        }
        __syncthreads();
    }

    // ---- softmax (8 warps x 4 rows) ----
    {
        int wid = tid >> 5, lane = tid & 31;
        for (int q = wid * 4; q < wid * 4 + 4; q++) {
            float* row = &S[q * SROW];
            float m = -1e30f;
            for (int c = lane; c < SROW; c += 32) m = fmaxf(m, row[c]);
            #pragma unroll
            for (int o = 16; o; o >>= 1) m = fmaxf(m, __shfl_xor_sync(0xffffffffu, m, o));
            float s = 0.f;
            for (int c = lane; c < SROW; c += 32) { float e = expf(row[c] - m); row[c] = e; s += e; }
            #pragma unroll
            for (int o = 16; o; o >>= 1) s += __shfl_xor_sync(0xffffffffu, s, o);
            float inv = 1.0f / s;
            for (int c = lane; c < SROW; c += 32) row[c] *= inv;
        }
    }
    __syncthreads();

    // ---- pass 2: O = P @ V ----
    float oacc[8];
    #pragma unroll
    for (int i = 0; i < 8; i++) oacc[i] = 0.f;
    int d = tid & 63;
    for (int t = 0; t < NKT; t++) {
        {
            int r = tid >> 2;
            int g = t * 64 + r;
            bool valid = g < KTOT;
            const float* src;
            if (g < Pv) src = pvb + (((size_t)(b * 2 + sel) * Pv + g) * Hv + h) * HDv;
            else        src = vb  + ((size_t)(b * Lv + (g - Pv)) * Hv + h) * HDv;
            int c = (tid & 3) * 4;
            #pragma unroll
            for (int p = 0; p < 4; p++) {
                int cc = c + p * 16;
                float4 v = valid ? *(const float4*)(src + cc) : make_float4(0.f, 0.f, 0.f, 0.f);
                *(float4*)&Ks[r * 68 + cc] = v;
            }
        }
        __syncthreads();
        #pragma unroll 4
        for (int k2 = 0; k2 < 64; k2++) {
            float vv = Ks[k2 * 68 + d];
            int col = t * 64 + k2;
            #pragma unroll
            for (int i = 0; i < 8; i++)
                oacc[i] += S[(qrb + i * 4) * SROW + col] * vv;
        }
        __syncthreads();
    }
    #pragma unroll
    for (int i = 0; i < 8; i++) {
        int q = qrb + i * 4;
        ob[((size_t)(b * Lv + q0 + q) * Hv + h) * HDv + d] = oacc[i];
    }
}

// ---------------- per-example adapter ---------------------------------------
__global__ __launch_bounds__(64) void adapter_down(
    const float* __restrict__ lz, const float* __restrict__ wd,
    const float* __restrict__ bd, float* __restrict__ az)
{
    int b = blockIdx.y, l = blockIdx.x, a = threadIdx.x;
    const float* xr = lz + (size_t)(b * Lv + l) * Dv;
    const float* wb = wd + (size_t)b * Dv * Av;
    float s = 0.f;
    #pragma unroll 4
    for (int dd = 0; dd < Dv; dd++) s += xr[dd] * wb[dd * Av + a];
    s += bd[b * Av + a];
    az[(size_t)(b * Lv + l) * Av + a] = gelu_f(s);
}

__global__ __launch_bounds__(256) void adapter_up(
    const float* __restrict__ az, const float* __restrict__ wu,
    const float* __restrict__ bu, float* __restrict__ out)
{
    int b = blockIdx.y, l = blockIdx.x;
    __shared__ float ash[Av];
    int tid = threadIdx.x;
    if (tid < Av) ash[tid] = az[(size_t)(b * Lv + l) * Av + tid];
    __syncthreads();
    const float* wb = wu + (size_t)b * Av * Dv;
    size_t o = (size_t)(b * Lv + l) * Dv;
    for (int dd = tid; dd < Dv; dd += 256) {
        float s = bu[b * Dv + dd];
        #pragma unroll 8
        for (int a = 0; a < Av; a++) s += ash[a] * wb[a * Dv + dd];
        out[o + dd] += s;
    }
}

// ---------------- driver -----------------------------------------------------
extern "C" void kernel_launch(void* const* d_in, const int* in_sizes, int n_in,
                              void* d_out, int out_size)
{
    const float* inputs  = (const float*)d_in[0];
    const float* encoded = (const float*)d_in[1];
    const float* awd     = (const float*)d_in[2];
    const float* awu     = (const float*)d_in[3];
    const float* abd     = (const float*)d_in[4];
    const float* abu     = (const float*)d_in[5];
    const float* pk      = (const float*)d_in[6];
    const float* pvv     = (const float*)d_in[7];
    const float* ln1     = (const float*)d_in[8];
    const float* ln2     = (const float*)d_in[9];
    const float* ln3     = (const float*)d_in[10];
    const float* sa_wq   = (const float*)d_in[11];
    const float* sa_wk   = (const float*)d_in[12];
    const float* sa_wv   = (const float*)d_in[13];
    const float* sa_wo   = (const float*)d_in[14];
    const float* ca_wq   = (const float*)d_in[15];
    const float* ca_wk   = (const float*)d_in[16];
    const float* ca_wv   = (const float*)d_in[17];
    const float* ca_wo   = (const float*)d_in[18];
    const float* relpos  = (const float*)d_in[19];
    const float* wi0     = (const float*)d_in[20];
    const float* wi1     = (const float*)d_in[21];
    const float* wo_mlp  = (const float*)d_in[22];
    // d_in[23] decoder_mask (causal tril — computed analytically)
    // d_in[24] encoder_decoder_mask (all true — ignored)
    float* out = (float*)d_out;

    float *xn, *q, *k, *v, *att, *x, *y, *h0, *h1, *az;
    cudaGetSymbolAddress((void**)&xn,  g_xn);
    cudaGetSymbolAddress((void**)&q,   g_q);
    cudaGetSymbolAddress((void**)&k,   g_k);
    cudaGetSymbolAddress((void**)&v,   g_v);
    cudaGetSymbolAddress((void**)&att, g_att);
    cudaGetSymbolAddress((void**)&x,   g_x);
    cudaGetSymbolAddress((void**)&y,   g_y);
    cudaGetSymbolAddress((void**)&h0,  g_h0);
    cudaGetSymbolAddress((void**)&h1,  g_h1);
    cudaGetSymbolAddress((void**)&az,  g_az);

    cudaFuncSetAttribute(attn_kernel, cudaFuncAttributeMaxDynamicSharedMemorySize, ATTN_SMEM);

    const int M = Bv * Lv;              // 4096
    dim3 g8(8, 32), g22(22, 32);
    dim3 ga(32, Bv * Hv);
    const float qs = 0.125f;            // HD^-0.5

    // self-attention block
    rmsnorm_kernel<<<M, 256>>>(inputs, ln1, xn);
    sgemm_kernel<<<g8, 256>>>(xn, sa_wq, q, M, 1024, 1024, qs,  nullptr, nullptr);
    sgemm_kernel<<<g8, 256>>>(xn, sa_wk, k, M, 1024, 1024, 1.f, nullptr, nullptr);
    sgemm_kernel<<<g8, 256>>>(xn, sa_wv, v, M, 1024, 1024, 1.f, nullptr, nullptr);
    attn_kernel<<<ga, 256, ATTN_SMEM>>>(q, k, v, pk, pvv, relpos, att, 0, 1);
    sgemm_kernel<<<g8, 256>>>(att, sa_wo, x, M, 1024, 1024, 1.f, inputs, nullptr);

    // cross-attention block
    rmsnorm_kernel<<<M, 256>>>(x, ln2, xn);
    sgemm_kernel<<<g8, 256>>>(xn,      ca_wq, q, M, 1024, 1024, qs,  nullptr, nullptr);
    sgemm_kernel<<<g8, 256>>>(encoded, ca_wk, k, M, 1024, 1024, 1.f, nullptr, nullptr);
    sgemm_kernel<<<g8, 256>>>(encoded, ca_wv, v, M, 1024, 1024, 1.f, nullptr, nullptr);
    attn_kernel<<<ga, 256, ATTN_SMEM>>>(q, k, v, pk, pvv, relpos, att, 1, 0);
    sgemm_kernel<<<g8, 256>>>(att, ca_wo, y, M, 1024, 1024, 1.f, x, nullptr);

    // MLP + adapter
    rmsnorm_kernel<<<M, 256>>>(y, ln3, xn);     // xn = lz
    sgemm_kernel<<<g22, 256>>>(xn, wi0, h0, M, Fv, 1024, 1.f, nullptr, nullptr);
    sgemm_kernel<<<g22, 256>>>(xn, wi1, h1, M, Fv, 1024, 1.f, nullptr, h0);   // h1 = gelu(h0)*h1
    sgemm_kernel<<<g8, 256>>>(h1, wo_mlp, out, M, 1024, Fv, 1.f, y, nullptr); // out = mlp + y
    adapter_down<<<dim3(Lv, Bv), 64>>>(xn, awd, abd, az);
    adapter_up<<<dim3(Lv, Bv), 256>>>(az, awu, abu, out);
}

// round 2
// speedup vs baseline: 1.4249x; 1.4249x over previous
#include <cuda_runtime.h>
#include <cuda_bf16.h>
#include <math.h>

#define Bv 4
#define Lv 1024
#define Dv 1024
#define Hv 16
#define HDv 64
#define Fv 2816
#define Av 64
#define Pv 30
#define KTOT (Pv + Lv)          /* 1054 keys incl. prefix */
#define NKT 17                  /* ceil(1054/64) key tiles */
#define SROW 1088               /* NKT*64, padded score row */

// ---------------- scratch (static device globals; no allocations) ----------
__device__ float g_xn[Bv*Lv*Dv];
__device__ float g_q [Bv*Lv*Dv];
__device__ float g_k [Bv*Lv*Dv];
__device__ float g_v [Bv*Lv*Dv];
__device__ float g_att[Bv*Lv*Dv];
__device__ float g_x [Bv*Lv*Dv];
__device__ float g_y [Bv*Lv*Dv];
__device__ float g_h0[Bv*Lv*Fv];
__device__ float g_h1[Bv*Lv*Fv];
__device__ float g_az[Bv*Lv*Av];

__device__ __forceinline__ float gelu_f(float x) {
    float x3 = x * x * x;
    return 0.5f * x * (1.0f + tanhf(0.7978845608028654f * (x + 0.044715f * x3)));
}

// pack two floats into hi/lo bf16x2 words (bf16x3 split scheme)
__device__ __forceinline__ void split2(float f0, float f1, unsigned &hi, unsigned &lo) {
    __nv_bfloat162 h = __floats2bfloat162_rn(f0, f1);
    float r0 = f0 - __bfloat162float(h.x);
    float r1 = f1 - __bfloat162float(h.y);
    __nv_bfloat162 l = __floats2bfloat162_rn(r0, r1);
    hi = *reinterpret_cast<unsigned*>(&h);
    lo = *reinterpret_cast<unsigned*>(&l);
}

__device__ __forceinline__ void mma16816(float* c, const unsigned* a, const unsigned* b) {
    asm volatile(
        "mma.sync.aligned.m16n8k16.row.col.f32.bf16.bf16.f32 "
        "{%0,%1,%2,%3}, {%4,%5,%6,%7}, {%8,%9}, {%0,%1,%2,%3};\n"
        : "+f"(c[0]), "+f"(c[1]), "+f"(c[2]), "+f"(c[3])
        : "r"(a[0]), "r"(a[1]), "r"(a[2]), "r"(a[3]), "r"(b[0]), "r"(b[1]));
}

// ---------------- RMSNorm ---------------------------------------------------
__global__ __launch_bounds__(256) void rmsnorm_kernel(
    const float* __restrict__ x, const float* __restrict__ w, float* __restrict__ o)
{
    int row = blockIdx.x;
    const float* xr = x + (size_t)row * Dv;
    float* orow = o + (size_t)row * Dv;
    int tid = threadIdx.x;
    int d0 = tid * 4;
    float4 v = *(const float4*)&xr[d0];
    float s = v.x*v.x + v.y*v.y + v.z*v.z + v.w*v.w;
    #pragma unroll
    for (int off = 16; off; off >>= 1) s += __shfl_xor_sync(0xffffffffu, s, off);
    __shared__ float red[8];
    __shared__ float inv_s;
    if ((tid & 31) == 0) red[tid >> 5] = s;
    __syncthreads();
    if (tid == 0) {
        float t = 0.f;
        #pragma unroll
        for (int i = 0; i < 8; i++) t += red[i];
        inv_s = rsqrtf(t * (1.0f / Dv) + 1e-6f);
    }
    __syncthreads();
    float inv = inv_s;
    float4 wv = *(const float4*)&w[d0];
    float4 r;
    r.x = v.x*inv*wv.x; r.y = v.y*inv*wv.y; r.z = v.z*inv*wv.z; r.w = v.w*inv*wv.w;
    *(float4*)&orow[d0] = r;
}

// ---------------- bf16x3 tensor-core GEMM 128x128x32 ------------------------
// C[M,N] = epilogue( alpha * A[M,K] @ B[K,N] ), fp32 in/out, bf16x3 internally.
// epilogue: +res[idx] if res; then *gelu(gate[idx]) if gate.
// Requires: M%128==0, N%128==0, K%32==0.
__global__ __launch_bounds__(256, 2) void tgemm_kernel(
    const float* __restrict__ A, const float* __restrict__ B, float* __restrict__ C,
    int M, int N, int K, float alpha,
    const float* __restrict__ res, const float* __restrict__ gate)
{
    // stride 40 halves (=20 words): g*20+tig distinct mod 32 -> conflict-free frags
    __shared__ __align__(16) __nv_bfloat16 Ahi[128][40];
    __shared__ __align__(16) __nv_bfloat16 Alo[128][40];
    __shared__ __align__(16) __nv_bfloat16 Bhi[128][40];   // [n][k] (n-major)
    __shared__ __align__(16) __nv_bfloat16 Blo[128][40];

    int tid  = threadIdx.x;
    int m0   = blockIdx.y * 128;
    int n0   = blockIdx.x * 128;
    int wid  = tid >> 5, lane = tid & 31;
    int g    = lane >> 2, tig = lane & 3;
    int wm   = (wid & 1) * 64;    // warp m-offset (2 warps in m)
    int wn   = (wid >> 1) * 32;   // warp n-offset (4 warps in n)

    float acc[4][4][4];
    #pragma unroll
    for (int i = 0; i < 4; i++)
        #pragma unroll
        for (int j = 0; j < 4; j++)
            #pragma unroll
            for (int r = 0; r < 4; r++) acc[i][j][r] = 0.f;

    // B loader coords: each thread owns (n, 16 consecutive k)
    int bn = tid & 127;
    int bkg = tid >> 7;           // 0 or 1 -> k range [16*bkg, 16*bkg+16)

    for (int k0 = 0; k0 < K; k0 += 32) {
        // ---- stage A tile (128 x 32), row-major, split to hi/lo ----
        float4 areg[4];
        #pragma unroll
        for (int i = 0; i < 4; i++) {
            int v = tid + i * 256;
            int row = v >> 3, c4 = (v & 7) * 4;
            areg[i] = *(const float4*)&A[(size_t)(m0 + row) * K + k0 + c4];
        }
        // ---- stage B tile (32 x 128) transposed to n-major ----
        float breg[16];
        {
            const float* bp = &B[(size_t)(k0 + bkg * 16) * N + n0 + bn];
            #pragma unroll
            for (int j = 0; j < 16; j++) breg[j] = bp[(size_t)j * N];
        }
        __syncthreads();   // previous tile fully consumed
        #pragma unroll
        for (int i = 0; i < 4; i++) {
            int v = tid + i * 256;
            int row = v >> 3, c4 = (v & 7) * 4;
            unsigned h0, l0, h1, l1;
            split2(areg[i].x, areg[i].y, h0, l0);
            split2(areg[i].z, areg[i].w, h1, l1);
            *(uint2*)&Ahi[row][c4] = make_uint2(h0, h1);
            *(uint2*)&Alo[row][c4] = make_uint2(l0, l1);
        }
        {
            unsigned hp[8], lp[8];
            #pragma unroll
            for (int j = 0; j < 8; j++)
                split2(breg[2 * j], breg[2 * j + 1], hp[j], lp[j]);
            *(uint4*)&Bhi[bn][bkg * 16]     = make_uint4(hp[0], hp[1], hp[2], hp[3]);
            *(uint4*)&Bhi[bn][bkg * 16 + 8] = make_uint4(hp[4], hp[5], hp[6], hp[7]);
            *(uint4*)&Blo[bn][bkg * 16]     = make_uint4(lp[0], lp[1], lp[2], lp[3]);
            *(uint4*)&Blo[bn][bkg * 16 + 8] = make_uint4(lp[4], lp[5], lp[6], lp[7]);
        }
        __syncthreads();

        // ---- compute: 2 k-steps of m16n8k16 ----
        #pragma unroll
        for (int ks = 0; ks < 2; ks++) {
            int kb = ks * 16;
            unsigned bh[4][2], bl[4][2];
            #pragma unroll
            for (int nt = 0; nt < 4; nt++) {
                int n = wn + nt * 8 + g;
                bh[nt][0] = *(const unsigned*)&Bhi[n][kb + 2 * tig];
                bh[nt][1] = *(const unsigned*)&Bhi[n][kb + 2 * tig + 8];
                bl[nt][0] = *(const unsigned*)&Blo[n][kb + 2 * tig];
                bl[nt][1] = *(const unsigned*)&Blo[n][kb + 2 * tig + 8];
            }
            #pragma unroll
            for (int mt = 0; mt < 4; mt++) {
                int r = wm + mt * 16 + g;
                unsigned ah[4], al[4];
                ah[0] = *(const unsigned*)&Ahi[r][kb + 2 * tig];
                ah[1] = *(const unsigned*)&Ahi[r + 8][kb + 2 * tig];
                ah[2] = *(const unsigned*)&Ahi[r][kb + 2 * tig + 8];
                ah[3] = *(const unsigned*)&Ahi[r + 8][kb + 2 * tig + 8];
                al[0] = *(const unsigned*)&Alo[r][kb + 2 * tig];
                al[1] = *(const unsigned*)&Alo[r + 8][kb + 2 * tig];
                al[2] = *(const unsigned*)&Alo[r][kb + 2 * tig + 8];
                al[3] = *(const unsigned*)&Alo[r + 8][kb + 2 * tig + 8];
                #pragma unroll
                for (int nt = 0; nt < 4; nt++) {
                    mma16816(acc[mt][nt], ah, bh[nt]);  // hi*hi
                    mma16816(acc[mt][nt], ah, bl[nt]);  // hi*lo
                    mma16816(acc[mt][nt], al, bh[nt]);  // lo*hi
                }
            }
        }
        __syncthreads();
    }

    // ---- epilogue ----
    #pragma unroll
    for (int mt = 0; mt < 4; mt++) {
        #pragma unroll
        for (int half = 0; half < 2; half++) {
            int m = m0 + wm + mt * 16 + g + half * 8;
            #pragma unroll
            for (int nt = 0; nt < 4; nt++) {
                int n = n0 + wn + nt * 8 + 2 * tig;
                size_t idx = (size_t)m * N + n;
                float v0 = acc[mt][nt][half * 2 + 0] * alpha;
                float v1 = acc[mt][nt][half * 2 + 1] * alpha;
                if (res) {
                    float2 rv = *(const float2*)&res[idx];
                    v0 += rv.x; v1 += rv.y;
                }
                if (gate) {
                    float2 gv = *(const float2*)&gate[idx];
                    v0 *= gelu_f(gv.x); v1 *= gelu_f(gv.y);
                }
                float2 o; o.x = v0; o.y = v1;
                *(float2*)&C[idx] = o;
            }
        }
    }
}

// ---------------- Attention (two-pass, prefix KV, optional causal+bias) -----
#define ATTN_SMEM ((32*SROW + 32*64 + 64*68 + 32) * 4)

__global__ __launch_bounds__(256) void attn_kernel(
    const float* __restrict__ qb, const float* __restrict__ kb, const float* __restrict__ vb,
    const float* __restrict__ pkb, const float* __restrict__ pvb,
    const float* __restrict__ relpos, float* __restrict__ ob,
    int sel, int causal)
{
    extern __shared__ float sm[];
    float* S      = sm;                    // [32][SROW]
    float* Qs     = S + 32 * SROW;         // [32][64]
    float* Ks     = Qs + 32 * 64;          // [64][68] (reused for V)
    float* relrow = Ks + 64 * 68;          // [32]

    int tid = threadIdx.x;
    int bh = blockIdx.y;
    int b = bh >> 4, h = bh & 15;
    int q0 = blockIdx.x * 32;

    {
        int r  = tid >> 3;
        int c0 = (tid & 7) * 8;
        const float* src = qb + ((size_t)(b * Lv + q0 + r) * Hv + h) * HDv + c0;
        float4 v0 = *(const float4*)src;
        float4 v1 = *(const float4*)(src + 4);
        *(float4*)&Qs[r * 64 + c0]     = v0;
        *(float4*)&Qs[r * 64 + c0 + 4] = v1;
    }
    if (causal && tid < 32) relrow[tid] = relpos[h * 32 + tid];
    __syncthreads();

    int qrb = tid >> 6;
    int kk  = tid & 63;

    for (int t = 0; t < NKT; t++) {
        {
            int r = tid >> 2;
            int g = t * 64 + r;
            bool valid = g < KTOT;
            const float* src;
            if (g < Pv) src = pkb + (((size_t)(b * 2 + sel) * Pv + g) * Hv + h) * HDv;
            else        src = kb  + ((size_t)(b * Lv + (g - Pv)) * Hv + h) * HDv;
            int c = (tid & 3) * 4;
            #pragma unroll
            for (int p = 0; p < 4; p++) {
                int cc = c + p * 16;
                float4 v = valid ? *(const float4*)(src + cc) : make_float4(0.f, 0.f, 0.f, 0.f);
                *(float4*)&Ks[r * 68 + cc] = v;
            }
        }
        __syncthreads();

        float sc[8];
        #pragma unroll
        for (int i = 0; i < 8; i++) sc[i] = 0.f;
        #pragma unroll
        for (int db = 0; db < 64; db += 16) {
            float kr[16];
            #pragma unroll
            for (int u = 0; u < 16; u += 4) {
                float4 v = *(const float4*)&Ks[kk * 68 + db + u];
                kr[u] = v.x; kr[u+1] = v.y; kr[u+2] = v.z; kr[u+3] = v.w;
            }
            #pragma unroll
            for (int i = 0; i < 8; i++) {
                const float* qp = &Qs[(qrb + i * 4) * 64 + db];
                #pragma unroll
                for (int u = 0; u < 16; u += 4) {
                    float4 v = *(const float4*)(qp + u);
                    sc[i] += v.x * kr[u] + v.y * kr[u+1] + v.z * kr[u+2] + v.w * kr[u+3];
                }
            }
        }
        int g = t * 64 + kk;
        #pragma unroll
        for (int i = 0; i < 8; i++) {
            int q = qrb + i * 4;
            float val = sc[i];
            if (g >= KTOT) {
                val = -1e10f;
            } else if (causal && g >= Pv) {
                int kp = g - Pv;
                int qp = q0 + q;
                if (kp > qp) val = -1e10f;
                else {
                    int rel = qp - kp;
                    int bkt;
                    if (rel < 16) bkt = rel;
                    else {
                        bkt = 16 + (int)(logf((float)rel * 0.0625f) *
                                         (16.0f / 2.0794415416798357f));
                        if (bkt > 31) bkt = 31;
                    }
                    val += relrow[bkt];
                }
            }
            S[q * SROW + g] = val;
        }
        __syncthreads();
    }

    {
        int wid = tid >> 5, lane = tid & 31;
        for (int q = wid * 4; q < wid * 4 + 4; q++) {
            float* row = &S[q * SROW];
            float m = -1e30f;
            for (int c = lane; c < SROW; c += 32) m = fmaxf(m, row[c]);
            #pragma unroll
            for (int o = 16; o; o >>= 1) m = fmaxf(m, __shfl_xor_sync(0xffffffffu, m, o));
            float s = 0.f;
            for (int c = lane; c < SROW; c += 32) { float e = expf(row[c] - m); row[c] = e; s += e; }
            #pragma unroll
            for (int o = 16; o; o >>= 1) s += __shfl_xor_sync(0xffffffffu, s, o);
            float inv = 1.0f / s;
            for (int c = lane; c < SROW; c += 32) row[c] *= inv;
        }
    }
    __syncthreads();

    float oacc[8];
    #pragma unroll
    for (int i = 0; i < 8; i++) oacc[i] = 0.f;
    int d = tid & 63;
    for (int t = 0; t < NKT; t++) {
        {
            int r = tid >> 2;
            int g = t * 64 + r;
            bool valid = g < KTOT;
            const float* src;
            if (g < Pv) src = pvb + (((size_t)(b * 2 + sel) * Pv + g) * Hv + h) * HDv;
            else        src = vb  + ((size_t)(b * Lv + (g - Pv)) * Hv + h) * HDv;
            int c = (tid & 3) * 4;
            #pragma unroll
            for (int p = 0; p < 4; p++) {
                int cc = c + p * 16;
                float4 v = valid ? *(const float4*)(src + cc) : make_float4(0.f, 0.f, 0.f, 0.f);
                *(float4*)&Ks[r * 68 + cc] = v;
            }
        }
        __syncthreads();
        #pragma unroll 4
        for (int k2 = 0; k2 < 64; k2++) {
            float vv = Ks[k2 * 68 + d];
            int col = t * 64 + k2;
            #pragma unroll
            for (int i = 0; i < 8; i++)
                oacc[i] += S[(qrb + i * 4) * SROW + col] * vv;
        }
        __syncthreads();
    }
    #pragma unroll
    for (int i = 0; i < 8; i++) {
        int q = qrb + i * 4;
        ob[((size_t)(b * Lv + q0 + q) * Hv + h) * HDv + d] = oacc[i];
    }
}

// ---------------- per-example adapter ---------------------------------------
__global__ __launch_bounds__(64) void adapter_down(
    const float* __restrict__ lz, const float* __restrict__ wd,
    const float* __restrict__ bd, float* __restrict__ az)
{
    int b = blockIdx.y, l = blockIdx.x, a = threadIdx.x;
    const float* xr = lz + (size_t)(b * Lv + l) * Dv;
    const float* wb = wd + (size_t)b * Dv * Av;
    float s = 0.f;
    #pragma unroll 4
    for (int dd = 0; dd < Dv; dd++) s += xr[dd] * wb[dd * Av + a];
    s += bd[b * Av + a];
    az[(size_t)(b * Lv + l) * Av + a] = gelu_f(s);
}

__global__ __launch_bounds__(256) void adapter_up(
    const float* __restrict__ az, const float* __restrict__ wu,
    const float* __restrict__ bu, float* __restrict__ out)
{
    int b = blockIdx.y, l = blockIdx.x;
    __shared__ float ash[Av];
    int tid = threadIdx.x;
    if (tid < Av) ash[tid] = az[(size_t)(b * Lv + l) * Av + tid];
    __syncthreads();
    const float* wb = wu + (size_t)b * Av * Dv;
    size_t o = (size_t)(b * Lv + l) * Dv;
    for (int dd = tid; dd < Dv; dd += 256) {
        float s = bu[b * Dv + dd];
        #pragma unroll 8
        for (int a = 0; a < Av; a++) s += ash[a] * wb[a * Dv + dd];
        out[o + dd] += s;
    }
}

// ---------------- driver -----------------------------------------------------
extern "C" void kernel_launch(void* const* d_in, const int* in_sizes, int n_in,
                              void* d_out, int out_size)
{
    const float* inputs  = (const float*)d_in[0];
    const float* encoded = (const float*)d_in[1];
    const float* awd     = (const float*)d_in[2];
    const float* awu     = (const float*)d_in[3];
    const float* abd     = (const float*)d_in[4];
    const float* abu     = (const float*)d_in[5];
    const float* pk      = (const float*)d_in[6];
    const float* pvv     = (const float*)d_in[7];
    const float* ln1     = (const float*)d_in[8];
    const float* ln2     = (const float*)d_in[9];
    const float* ln3     = (const float*)d_in[10];
    const float* sa_wq   = (const float*)d_in[11];
    const float* sa_wk   = (const float*)d_in[12];
    const float* sa_wv   = (const float*)d_in[13];
    const float* sa_wo   = (const float*)d_in[14];
    const float* ca_wq   = (const float*)d_in[15];
    const float* ca_wk   = (const float*)d_in[16];
    const float* ca_wv   = (const float*)d_in[17];
    const float* ca_wo   = (const float*)d_in[18];
    const float* relpos  = (const float*)d_in[19];
    const float* wi0     = (const float*)d_in[20];
    const float* wi1     = (const float*)d_in[21];
    const float* wo_mlp  = (const float*)d_in[22];
    float* out = (float*)d_out;

    float *xn, *q, *k, *v, *att, *x, *y, *h0, *h1, *az;
    cudaGetSymbolAddress((void**)&xn,  g_xn);
    cudaGetSymbolAddress((void**)&q,   g_q);
    cudaGetSymbolAddress((void**)&k,   g_k);
    cudaGetSymbolAddress((void**)&v,   g_v);
    cudaGetSymbolAddress((void**)&att, g_att);
    cudaGetSymbolAddress((void**)&x,   g_x);
    cudaGetSymbolAddress((void**)&y,   g_y);
    cudaGetSymbolAddress((void**)&h0,  g_h0);
    cudaGetSymbolAddress((void**)&h1,  g_h1);
    cudaGetSymbolAddress((void**)&az,  g_az);

    cudaFuncSetAttribute(attn_kernel, cudaFuncAttributeMaxDynamicSharedMemorySize, ATTN_SMEM);

    const int M = Bv * Lv;              // 4096
    dim3 g8(8, 32), g22(22, 32);
    dim3 ga(32, Bv * Hv);
    const float qs = 0.125f;            // HD^-0.5

    // self-attention block
    rmsnorm_kernel<<<M, 256>>>(inputs, ln1, xn);
    tgemm_kernel<<<g8, 256>>>(xn, sa_wq, q, M, 1024, 1024, qs,  nullptr, nullptr);
    tgemm_kernel<<<g8, 256>>>(xn, sa_wk, k, M, 1024, 1024, 1.f, nullptr, nullptr);
    tgemm_kernel<<<g8, 256>>>(xn, sa_wv, v, M, 1024, 1024, 1.f, nullptr, nullptr);
    attn_kernel<<<ga, 256, ATTN_SMEM>>>(q, k, v, pk, pvv, relpos, att, 0, 1);
    tgemm_kernel<<<g8, 256>>>(att, sa_wo, x, M, 1024, 1024, 1.f, inputs, nullptr);

    // cross-attention block
    rmsnorm_kernel<<<M, 256>>>(x, ln2, xn);
    tgemm_kernel<<<g8, 256>>>(xn,      ca_wq, q, M, 1024, 1024, qs,  nullptr, nullptr);
    tgemm_kernel<<<g8, 256>>>(encoded, ca_wk, k, M, 1024, 1024, 1.f, nullptr, nullptr);
    tgemm_kernel<<<g8, 256>>>(encoded, ca_wv, v, M, 1024, 1024, 1.f, nullptr, nullptr);
    attn_kernel<<<ga, 256, ATTN_SMEM>>>(q, k, v, pk, pvv, relpos, att, 1, 0);
    tgemm_kernel<<<g8, 256>>>(att, ca_wo, y, M, 1024, 1024, 1.f, x, nullptr);

    // MLP + adapter
    rmsnorm_kernel<<<M, 256>>>(y, ln3, xn);     // xn = lz
    tgemm_kernel<<<g22, 256>>>(xn, wi0, h0, M, Fv, 1024, 1.f, nullptr, nullptr);
    tgemm_kernel<<<g22, 256>>>(xn, wi1, h1, M, Fv, 1024, 1.f, nullptr, h0);   // h1 = gelu(h0)*h1
    tgemm_kernel<<<g8, 256>>>(h1, wo_mlp, out, M, 1024, Fv, 1.f, y, nullptr); // out = mlp + y
    adapter_down<<<dim3(Lv, Bv), 64>>>(xn, awd, abd, az);
    adapter_up<<<dim3(Lv, Bv), 256>>>(az, awu, abu, out);
}

// round 3
// speedup vs baseline: 1.8639x; 1.3080x over previous
#include <cuda_runtime.h>
#include <cuda_bf16.h>
#include <math.h>

#define Bv 4
#define Lv 1024
#define Dv 1024
#define Hv 16
#define HDv 64
#define Fv 2816
#define Av 64
#define Pv 30
#define KTOT (Pv + Lv)          /* 1054 keys incl. prefix */
#define NKT 17                  /* ceil(1054/64) key tiles */

// ---------------- scratch (static device globals; no allocations) ----------
__device__ float g_xn[Bv*Lv*Dv];
__device__ float g_q [Bv*Lv*Dv];
__device__ float g_k [Bv*Lv*Dv];
__device__ float g_v [Bv*Lv*Dv];
__device__ float g_att[Bv*Lv*Dv];
__device__ float g_x [Bv*Lv*Dv];
__device__ float g_y [Bv*Lv*Dv];
__device__ float g_h0[Bv*Lv*Fv];
__device__ float g_h1[Bv*Lv*Fv];
__device__ float g_az[Bv*Lv*Av];

__device__ __forceinline__ float gelu_f(float x) {
    float x3 = x * x * x;
    return 0.5f * x * (1.0f + tanhf(0.7978845608028654f * (x + 0.044715f * x3)));
}

// pack two floats into hi/lo bf16x2 words (bf16x3 split scheme)
__device__ __forceinline__ void split2(float f0, float f1, unsigned &hi, unsigned &lo) {
    __nv_bfloat162 h = __floats2bfloat162_rn(f0, f1);
    float r0 = f0 - __bfloat162float(h.x);
    float r1 = f1 - __bfloat162float(h.y);
    __nv_bfloat162 l = __floats2bfloat162_rn(r0, r1);
    hi = *reinterpret_cast<unsigned*>(&h);
    lo = *reinterpret_cast<unsigned*>(&l);
}

__device__ __forceinline__ void mma16816(float* c, const unsigned* a, const unsigned* b) {
    asm volatile(
        "mma.sync.aligned.m16n8k16.row.col.f32.bf16.bf16.f32 "
        "{%0,%1,%2,%3}, {%4,%5,%6,%7}, {%8,%9}, {%0,%1,%2,%3};\n"
        : "+f"(c[0]), "+f"(c[1]), "+f"(c[2]), "+f"(c[3])
        : "r"(a[0]), "r"(a[1]), "r"(a[2]), "r"(a[3]), "r"(b[0]), "r"(b[1]));
}

// ---------------- RMSNorm ---------------------------------------------------
__global__ __launch_bounds__(256) void rmsnorm_kernel(
    const float* __restrict__ x, const float* __restrict__ w, float* __restrict__ o)
{
    int row = blockIdx.x;
    const float* xr = x + (size_t)row * Dv;
    float* orow = o + (size_t)row * Dv;
    int tid = threadIdx.x;
    int d0 = tid * 4;
    float4 v = *(const float4*)&xr[d0];
    float s = v.x*v.x + v.y*v.y + v.z*v.z + v.w*v.w;
    #pragma unroll
    for (int off = 16; off; off >>= 1) s += __shfl_xor_sync(0xffffffffu, s, off);
    __shared__ float red[8];
    __shared__ float inv_s;
    if ((tid & 31) == 0) red[tid >> 5] = s;
    __syncthreads();
    if (tid == 0) {
        float t = 0.f;
        #pragma unroll
        for (int i = 0; i < 8; i++) t += red[i];
        inv_s = rsqrtf(t * (1.0f / Dv) + 1e-6f);
    }
    __syncthreads();
    float inv = inv_s;
    float4 wv = *(const float4*)&w[d0];
    float4 r;
    r.x = v.x*inv*wv.x; r.y = v.y*inv*wv.y; r.z = v.z*inv*wv.z; r.w = v.w*inv*wv.w;
    *(float4*)&orow[d0] = r;
}

// ---------------- bf16x3 tensor-core GEMM 128x128x32 ------------------------
__global__ __launch_bounds__(256, 2) void tgemm_kernel(
    const float* __restrict__ A, const float* __restrict__ B, float* __restrict__ C,
    int M, int N, int K, float alpha,
    const float* __restrict__ res, const float* __restrict__ gate)
{
    __shared__ __align__(16) __nv_bfloat16 Ahi[128][40];
    __shared__ __align__(16) __nv_bfloat16 Alo[128][40];
    __shared__ __align__(16) __nv_bfloat16 Bhi[128][40];   // [n][k] (n-major)
    __shared__ __align__(16) __nv_bfloat16 Blo[128][40];

    int tid  = threadIdx.x;
    int m0   = blockIdx.y * 128;
    int n0   = blockIdx.x * 128;
    int wid  = tid >> 5, lane = tid & 31;
    int g    = lane >> 2, tig = lane & 3;
    int wm   = (wid & 1) * 64;
    int wn   = (wid >> 1) * 32;

    float acc[4][4][4];
    #pragma unroll
    for (int i = 0; i < 4; i++)
        #pragma unroll
        for (int j = 0; j < 4; j++)
            #pragma unroll
            for (int r = 0; r < 4; r++) acc[i][j][r] = 0.f;

    int bn = tid & 127;
    int bkg = tid >> 7;

    for (int k0 = 0; k0 < K; k0 += 32) {
        float4 areg[4];
        #pragma unroll
        for (int i = 0; i < 4; i++) {
            int v = tid + i * 256;
            int row = v >> 3, c4 = (v & 7) * 4;
            areg[i] = *(const float4*)&A[(size_t)(m0 + row) * K + k0 + c4];
        }
        float breg[16];
        {
            const float* bp = &B[(size_t)(k0 + bkg * 16) * N + n0 + bn];
            #pragma unroll
            for (int j = 0; j < 16; j++) breg[j] = bp[(size_t)j * N];
        }
        __syncthreads();
        #pragma unroll
        for (int i = 0; i < 4; i++) {
            int v = tid + i * 256;
            int row = v >> 3, c4 = (v & 7) * 4;
            unsigned h0, l0, h1, l1;
            split2(areg[i].x, areg[i].y, h0, l0);
            split2(areg[i].z, areg[i].w, h1, l1);
            *(uint2*)&Ahi[row][c4] = make_uint2(h0, h1);
            *(uint2*)&Alo[row][c4] = make_uint2(l0, l1);
        }
        {
            unsigned hp[8], lp[8];
            #pragma unroll
            for (int j = 0; j < 8; j++)
                split2(breg[2 * j], breg[2 * j + 1], hp[j], lp[j]);
            *(uint4*)&Bhi[bn][bkg * 16]     = make_uint4(hp[0], hp[1], hp[2], hp[3]);
            *(uint4*)&Bhi[bn][bkg * 16 + 8] = make_uint4(hp[4], hp[5], hp[6], hp[7]);
            *(uint4*)&Blo[bn][bkg * 16]     = make_uint4(lp[0], lp[1], lp[2], lp[3]);
            *(uint4*)&Blo[bn][bkg * 16 + 8] = make_uint4(lp[4], lp[5], lp[6], lp[7]);
        }
        __syncthreads();

        #pragma unroll
        for (int ks = 0; ks < 2; ks++) {
            int kb = ks * 16;
            unsigned bh[4][2], bl[4][2];
            #pragma unroll
            for (int nt = 0; nt < 4; nt++) {
                int n = wn + nt * 8 + g;
                bh[nt][0] = *(const unsigned*)&Bhi[n][kb + 2 * tig];
                bh[nt][1] = *(const unsigned*)&Bhi[n][kb + 2 * tig + 8];
                bl[nt][0] = *(const unsigned*)&Blo[n][kb + 2 * tig];
                bl[nt][1] = *(const unsigned*)&Blo[n][kb + 2 * tig + 8];
            }
            #pragma unroll
            for (int mt = 0; mt < 4; mt++) {
                int r = wm + mt * 16 + g;
                unsigned ah[4], al[4];
                ah[0] = *(const unsigned*)&Ahi[r][kb + 2 * tig];
                ah[1] = *(const unsigned*)&Ahi[r + 8][kb + 2 * tig];
                ah[2] = *(const unsigned*)&Ahi[r][kb + 2 * tig + 8];
                ah[3] = *(const unsigned*)&Ahi[r + 8][kb + 2 * tig + 8];
                al[0] = *(const unsigned*)&Alo[r][kb + 2 * tig];
                al[1] = *(const unsigned*)&Alo[r + 8][kb + 2 * tig];
                al[2] = *(const unsigned*)&Alo[r][kb + 2 * tig + 8];
                al[3] = *(const unsigned*)&Alo[r + 8][kb + 2 * tig + 8];
                #pragma unroll
                for (int nt = 0; nt < 4; nt++) {
                    mma16816(acc[mt][nt], ah, bh[nt]);
                    mma16816(acc[mt][nt], ah, bl[nt]);
                    mma16816(acc[mt][nt], al, bh[nt]);
                }
            }
        }
        __syncthreads();
    }

    #pragma unroll
    for (int mt = 0; mt < 4; mt++) {
        #pragma unroll
        for (int half = 0; half < 2; half++) {
            int m = m0 + wm + mt * 16 + g + half * 8;
            #pragma unroll
            for (int nt = 0; nt < 4; nt++) {
                int n = n0 + wn + nt * 8 + 2 * tig;
                size_t idx = (size_t)m * N + n;
                float v0 = acc[mt][nt][half * 2 + 0] * alpha;
                float v1 = acc[mt][nt][half * 2 + 1] * alpha;
                if (res) {
                    float2 rv = *(const float2*)&res[idx];
                    v0 += rv.x; v1 += rv.y;
                }
                if (gate) {
                    float2 gv = *(const float2*)&gate[idx];
                    v0 *= gelu_f(gv.x); v1 *= gelu_f(gv.y);
                }
                float2 o; o.x = v0; o.y = v1;
                *(float2*)&C[idx] = o;
            }
        }
    }
}

// ---------------- Flash attention (online softmax, prefix KV) ---------------
// grid: (L/32, B*H), block 256. q pre-scaled by HD^-0.5.
// smem: Q[32][64] + S[32][68] + K[64][68] + V[64][68] + 4x[32]  = ~52KB
#define FATTN_SMEM ((32*64 + 32*68 + 64*68 + 64*68 + 4*32) * 4)

__global__ __launch_bounds__(256, 3) void fattn_kernel(
    const float* __restrict__ qb, const float* __restrict__ kb, const float* __restrict__ vb,
    const float* __restrict__ pkb, const float* __restrict__ pvb,
    const float* __restrict__ relpos, float* __restrict__ ob,
    int sel, int causal)
{
    extern __shared__ float sm[];
    float* Qs     = sm;                    // [32][64]
    float* S      = Qs + 32 * 64;          // [32][68]
    float* Ks     = S + 32 * 68;           // [64][68]
    float* Vs     = Ks + 64 * 68;          // [64][68]
    float* relrow = Vs + 64 * 68;          // [32]
    float* rowm   = relrow + 32;           // [32] running max
    float* rowl   = rowm + 32;             // [32] running sum
    float* corr   = rowl + 32;             // [32] per-tile correction

    int tid = threadIdx.x;
    int bh = blockIdx.y;
    int b = bh >> 4, h = bh & 15;
    int q0 = blockIdx.x * 32;

    // load Q tile
    {
        int r  = tid >> 3;
        int c0 = (tid & 7) * 8;
        const float* src = qb + ((size_t)(b * Lv + q0 + r) * Hv + h) * HDv + c0;
        *(float4*)&Qs[r * 64 + c0]     = *(const float4*)src;
        *(float4*)&Qs[r * 64 + c0 + 4] = *(const float4*)(src + 4);
    }
    if (tid < 32) {
        if (causal) relrow[tid] = relpos[h * 32 + tid];
        rowm[tid] = -1e30f;
        rowl[tid] = 0.f;
    }
    __syncthreads();

    int qrb = tid >> 6;       // 0..3, constant per warp-pair
    int kk  = tid & 63;       // key index (scores) / head dim (PV)

    float oacc[8];
    #pragma unroll
    for (int i = 0; i < 8; i++) oacc[i] = 0.f;

    int ntile = causal ? (Pv + q0 + 32 + 63) >> 6 : NKT;

    for (int t = 0; t < ntile; t++) {
        // ---- stage K and V tiles ----
        {
            int r = tid >> 2;
            int g = t * 64 + r;
            bool valid = g < KTOT;
            const float *ks, *vs;
            if (g < Pv) {
                size_t off = (((size_t)(b * 2 + sel) * Pv + g) * Hv + h) * HDv;
                ks = pkb + off; vs = pvb + off;
            } else {
                size_t off = ((size_t)(b * Lv + (g - Pv)) * Hv + h) * HDv;
                ks = kb + off; vs = vb + off;
            }
            int c = (tid & 3) * 4;
            #pragma unroll
            for (int p = 0; p < 4; p++) {
                int cc = c + p * 16;
                float4 kv = valid ? *(const float4*)(ks + cc) : make_float4(0.f,0.f,0.f,0.f);
                float4 vv = valid ? *(const float4*)(vs + cc) : make_float4(0.f,0.f,0.f,0.f);
                *(float4*)&Ks[r * 68 + cc] = kv;
                *(float4*)&Vs[r * 68 + cc] = vv;
            }
        }
        __syncthreads();

        // ---- scores: 8 q-rows x 1 key per thread ----
        float sc[8];
        #pragma unroll
        for (int i = 0; i < 8; i++) sc[i] = 0.f;
        #pragma unroll
        for (int db = 0; db < 64; db += 16) {
            float kr[16];
            #pragma unroll
            for (int u = 0; u < 16; u += 4) {
                float4 v = *(const float4*)&Ks[kk * 68 + db + u];
                kr[u] = v.x; kr[u+1] = v.y; kr[u+2] = v.z; kr[u+3] = v.w;
            }
            #pragma unroll
            for (int i = 0; i < 8; i++) {
                const float* qp = &Qs[(qrb + i * 4) * 64 + db];
                #pragma unroll
                for (int u = 0; u < 16; u += 4) {
                    float4 v = *(const float4*)(qp + u);
                    sc[i] += v.x * kr[u] + v.y * kr[u+1] + v.z * kr[u+2] + v.w * kr[u+3];
                }
            }
        }
        {
            int g = t * 64 + kk;
            #pragma unroll
            for (int i = 0; i < 8; i++) {
                int q = qrb + i * 4;
                float val = sc[i];
                if (g >= KTOT) {
                    val = -1e10f;
                } else if (causal && g >= Pv) {
                    int kp = g - Pv;
                    int qp = q0 + q;
                    if (kp > qp) val = -1e10f;
                    else {
                        int rel = qp - kp;
                        int bkt;
                        if (rel < 16) bkt = rel;
                        else {
                            bkt = 16 + (int)(logf((float)rel * 0.0625f) *
                                             (16.0f / 2.0794415416798357f));
                            if (bkt > 31) bkt = 31;
                        }
                        val += relrow[bkt];
                    }
                }
                S[q * 68 + kk] = val;
            }
        }
        __syncthreads();

        // ---- online softmax update: warp w owns rows 4w..4w+3 ----
        {
            int wid = tid >> 5, lane = tid & 31;
            #pragma unroll
            for (int qi = 0; qi < 4; qi++) {
                int q = wid * 4 + qi;
                float* row = &S[q * 68];
                float v0 = row[lane], v1 = row[lane + 32];
                float tm = fmaxf(v0, v1);
                #pragma unroll
                for (int o = 16; o; o >>= 1) tm = fmaxf(tm, __shfl_xor_sync(0xffffffffu, tm, o));
                float mold = rowm[q];
                float mnew = fmaxf(mold, tm);
                float e0 = __expf(v0 - mnew), e1 = __expf(v1 - mnew);
                row[lane] = e0; row[lane + 32] = e1;
                float s = e0 + e1;
                #pragma unroll
                for (int o = 16; o; o >>= 1) s += __shfl_xor_sync(0xffffffffu, s, o);
                if (lane == 0) {
                    float c = __expf(mold - mnew);
                    rowm[q] = mnew;
                    rowl[q] = rowl[q] * c + s;
                    corr[q] = c;
                }
            }
        }
        __syncthreads();

        // ---- O update: oacc = oacc*corr + P@V ----
        int d = kk;
        #pragma unroll
        for (int i = 0; i < 8; i++) oacc[i] *= corr[qrb + i * 4];
        #pragma unroll 4
        for (int k2 = 0; k2 < 64; k2++) {
            float vv = Vs[k2 * 68 + d];
            #pragma unroll
            for (int i = 0; i < 8; i++)
                oacc[i] += S[(qrb + i * 4) * 68 + k2] * vv;
        }
        __syncthreads();
    }

    #pragma unroll
    for (int i = 0; i < 8; i++) {
        int q = qrb + i * 4;
        float inv = 1.0f / rowl[q];
        ob[((size_t)(b * Lv + q0 + q) * Hv + h) * HDv + kk] = oacc[i] * inv;
    }
}

// ---------------- per-example adapter ---------------------------------------
__global__ __launch_bounds__(64) void adapter_down(
    const float* __restrict__ lz, const float* __restrict__ wd,
    const float* __restrict__ bd, float* __restrict__ az)
{
    int b = blockIdx.y, l = blockIdx.x, a = threadIdx.x;
    const float* xr = lz + (size_t)(b * Lv + l) * Dv;
    const float* wb = wd + (size_t)b * Dv * Av;
    float s = 0.f;
    #pragma unroll 4
    for (int dd = 0; dd < Dv; dd++) s += xr[dd] * wb[dd * Av + a];
    s += bd[b * Av + a];
    az[(size_t)(b * Lv + l) * Av + a] = gelu_f(s);
}

__global__ __launch_bounds__(256) void adapter_up(
    const float* __restrict__ az, const float* __restrict__ wu,
    const float* __restrict__ bu, float* __restrict__ out)
{
    int b = blockIdx.y, l = blockIdx.x;
    __shared__ float ash[Av];
    int tid = threadIdx.x;
    if (tid < Av) ash[tid] = az[(size_t)(b * Lv + l) * Av + tid];
    __syncthreads();
    const float* wb = wu + (size_t)b * Av * Dv;
    size_t o = (size_t)(b * Lv + l) * Dv;
    for (int dd = tid; dd < Dv; dd += 256) {
        float s = bu[b * Dv + dd];
        #pragma unroll 8
        for (int a = 0; a < Av; a++) s += ash[a] * wb[a * Dv + dd];
        out[o + dd] += s;
    }
}

// ---------------- driver -----------------------------------------------------
extern "C" void kernel_launch(void* const* d_in, const int* in_sizes, int n_in,
                              void* d_out, int out_size)
{
    const float* inputs  = (const float*)d_in[0];
    const float* encoded = (const float*)d_in[1];
    const float* awd     = (const float*)d_in[2];
    const float* awu     = (const float*)d_in[3];
    const float* abd     = (const float*)d_in[4];
    const float* abu     = (const float*)d_in[5];
    const float* pk      = (const float*)d_in[6];
    const float* pvv     = (const float*)d_in[7];
    const float* ln1     = (const float*)d_in[8];
    const float* ln2     = (const float*)d_in[9];
    const float* ln3     = (const float*)d_in[10];
    const float* sa_wq   = (const float*)d_in[11];
    const float* sa_wk   = (const float*)d_in[12];
    const float* sa_wv   = (const float*)d_in[13];
    const float* sa_wo   = (const float*)d_in[14];
    const float* ca_wq   = (const float*)d_in[15];
    const float* ca_wk   = (const float*)d_in[16];
    const float* ca_wv   = (const float*)d_in[17];
    const float* ca_wo   = (const float*)d_in[18];
    const float* relpos  = (const float*)d_in[19];
    const float* wi0     = (const float*)d_in[20];
    const float* wi1     = (const float*)d_in[21];
    const float* wo_mlp  = (const float*)d_in[22];
    float* out = (float*)d_out;

    float *xn, *q, *k, *v, *att, *x, *y, *h0, *h1, *az;
    cudaGetSymbolAddress((void**)&xn,  g_xn);
    cudaGetSymbolAddress((void**)&q,   g_q);
    cudaGetSymbolAddress((void**)&k,   g_k);
    cudaGetSymbolAddress((void**)&v,   g_v);
    cudaGetSymbolAddress((void**)&att, g_att);
    cudaGetSymbolAddress((void**)&x,   g_x);
    cudaGetSymbolAddress((void**)&y,   g_y);
    cudaGetSymbolAddress((void**)&h0,  g_h0);
    cudaGetSymbolAddress((void**)&h1,  g_h1);
    cudaGetSymbolAddress((void**)&az,  g_az);

    cudaFuncSetAttribute(fattn_kernel, cudaFuncAttributeMaxDynamicSharedMemorySize, FATTN_SMEM);

    const int M = Bv * Lv;              // 4096
    dim3 g8(8, 32), g22(22, 32);
    dim3 ga(32, Bv * Hv);
    const float qs = 0.125f;            // HD^-0.5

    // self-attention block
    rmsnorm_kernel<<<M, 256>>>(inputs, ln1, xn);
    tgemm_kernel<<<g8, 256>>>(xn, sa_wq, q, M, 1024, 1024, qs,  nullptr, nullptr);
    tgemm_kernel<<<g8, 256>>>(xn, sa_wk, k, M, 1024, 1024, 1.f, nullptr, nullptr);
    tgemm_kernel<<<g8, 256>>>(xn, sa_wv, v, M, 1024, 1024, 1.f, nullptr, nullptr);
    fattn_kernel<<<ga, 256, FATTN_SMEM>>>(q, k, v, pk, pvv, relpos, att, 0, 1);
    tgemm_kernel<<<g8, 256>>>(att, sa_wo, x, M, 1024, 1024, 1.f, inputs, nullptr);

    // cross-attention block
    rmsnorm_kernel<<<M, 256>>>(x, ln2, xn);
    tgemm_kernel<<<g8, 256>>>(xn,      ca_wq, q, M, 1024, 1024, qs,  nullptr, nullptr);
    tgemm_kernel<<<g8, 256>>>(encoded, ca_wk, k, M, 1024, 1024, 1.f, nullptr, nullptr);
    tgemm_kernel<<<g8, 256>>>(encoded, ca_wv, v, M, 1024, 1024, 1.f, nullptr, nullptr);
    fattn_kernel<<<ga, 256, FATTN_SMEM>>>(q, k, v, pk, pvv, relpos, att, 1, 0);
    tgemm_kernel<<<g8, 256>>>(att, ca_wo, y, M, 1024, 1024, 1.f, x, nullptr);

    // MLP + adapter
    rmsnorm_kernel<<<M, 256>>>(y, ln3, xn);     // xn = lz
    tgemm_kernel<<<g22, 256>>>(xn, wi0, h0, M, Fv, 1024, 1.f, nullptr, nullptr);
    tgemm_kernel<<<g22, 256>>>(xn, wi1, h1, M, Fv, 1024, 1.f, nullptr, h0);   // h1 = gelu(h0)*h1
    tgemm_kernel<<<g8, 256>>>(h1, wo_mlp, out, M, 1024, Fv, 1.f, y, nullptr); // out = mlp + y
    adapter_down<<<dim3(Lv, Bv), 64>>>(xn, awd, abd, az);
    adapter_up<<<dim3(Lv, Bv), 256>>>(az, awu, abu, out);
}